// round 3
// baseline (speedup 1.0000x reference)
#include <cuda_runtime.h>
#include <cstdint>
#include <cstddef>

#define BD 128     // batch
#define TD 256     // seq len
#define HD 512     // hidden
#define G3 1536    // 3*H
#define LD 3       // layers
#define MD (BD*TD) // 32768 rows for input GEMM

// ---------------- scratch (static device allocations; no cudaMalloc) -------
__device__ float g_XP[(size_t)MD * G3];          // input projections, 201MB
__device__ float g_X1[(size_t)MD * HD];          // layer0 seq out
__device__ float g_X2[(size_t)MD * HD];          // layer1 seq out
__device__ float g_WuT[(size_t)LD * G3 * HD];    // transposed recurrent weights
__device__ float g_hT[2 * HD * BD];              // ping-pong hidden state, [j][b] layout
__device__ unsigned int g_bar;                   // grid barrier counter

// ---------------- helpers --------------------------------------------------
__device__ __forceinline__ void cp16(float* dst, const float* src) {
    unsigned s = (unsigned)__cvta_generic_to_shared(dst);
    asm volatile("cp.async.cg.shared.global [%0], [%1], 16;\n" :: "r"(s), "l"(src) : "memory");
}

// ---------------- transpose rec_kernels: [L][512][1536] -> [L][1536][512] --
__global__ void k_trans(const float* __restrict__ in, float* __restrict__ out) {
    __shared__ float s[32][33];
    const int l  = blockIdx.z;
    const int n0 = blockIdx.x * 32;
    const int k0 = blockIdx.y * 32;
    const float* inl  = in  + (size_t)l * HD * G3;
    float*       outl = out + (size_t)l * G3 * HD;
    for (int r = threadIdx.y; r < 32; r += 8)
        s[r][threadIdx.x] = inl[(size_t)(k0 + r) * G3 + n0 + threadIdx.x];
    __syncthreads();
    for (int r = threadIdx.y; r < 32; r += 8)
        outl[(size_t)(n0 + r) * HD + k0 + threadIdx.x] = s[threadIdx.x][r];
}

// ---------------- misc tiny kernels ---------------------------------------
__global__ void k_zero(float* p, int n) {
    int i = blockIdx.x * blockDim.x + threadIdx.x;
    if (i < n) p[i] = 0.0f;
}
__global__ void k_rst() { g_bar = 0u; }

// final state: d_out tail [b][j] from hT [j][b]
__global__ void k_final(const float* __restrict__ hT0, float* __restrict__ out) {
    int idx = blockIdx.x * blockDim.x + threadIdx.x;  // 65536
    int b = idx >> 9, j = idx & 511;
    out[idx] = hT0[(size_t)j * BD + b];
}

// ---------------- input GEMM: C[M,1536] = A[M,512] @ Bw[512,1536] + bias ---
__global__ __launch_bounds__(256, 1)
void k_gemm(const float* __restrict__ A, const float* __restrict__ Bw,
            const float* __restrict__ bias, float* __restrict__ C) {
    __shared__ float As[16][132];   // [k][m] padded
    __shared__ float Bs[16][128];   // [k][n]
    const int tid = threadIdx.x;
    const int n0 = blockIdx.x * 128;
    const int m0 = blockIdx.y * 128;
    const int tx = tid & 15;
    const int ty = tid >> 4;
    const int arow = tid >> 2;      // 0..63
    const int af   = tid & 3;       // k-float4 slot
    const int brow = tid >> 4;      // 0..15
    const int bf   = tid & 15;

    float acc[8][8];
#pragma unroll
    for (int i = 0; i < 8; i++)
#pragma unroll
        for (int jj = 0; jj < 8; jj++) acc[i][jj] = 0.0f;

    for (int k0 = 0; k0 < 512; k0 += 16) {
#pragma unroll
        for (int p = 0; p < 2; p++) {
            float4 v = *(const float4*)(A + (size_t)(m0 + arow + p * 64) * HD + k0 + af * 4);
            As[af * 4 + 0][arow + p * 64] = v.x;
            As[af * 4 + 1][arow + p * 64] = v.y;
            As[af * 4 + 2][arow + p * 64] = v.z;
            As[af * 4 + 3][arow + p * 64] = v.w;
        }
        // FIX (R1 bug): load BOTH 64-col halves of Bs (was loading only cols 0..63,
        // leaving Bs[k][64..127] uninitialized -> rel_err 2.88)
#pragma unroll
        for (int p = 0; p < 2; p++) {
            *(float4*)&Bs[brow][p * 64 + bf * 4] =
                *(const float4*)(Bw + (size_t)(k0 + brow) * G3 + n0 + p * 64 + bf * 4);
        }
        __syncthreads();
#pragma unroll
        for (int k = 0; k < 16; k++) {
            float a0[8], b0r[8];
            *(float4*)&a0[0]  = *(const float4*)&As[k][ty * 4];
            *(float4*)&a0[4]  = *(const float4*)&As[k][ty * 4 + 64];
            *(float4*)&b0r[0] = *(const float4*)&Bs[k][tx * 4];
            *(float4*)&b0r[4] = *(const float4*)&Bs[k][tx * 4 + 64];
#pragma unroll
            for (int i = 0; i < 8; i++)
#pragma unroll
                for (int jj = 0; jj < 8; jj++) acc[i][jj] += a0[i] * b0r[jj];
        }
        __syncthreads();
    }
    float bv[8];
#pragma unroll
    for (int jj = 0; jj < 4; jj++) {
        bv[jj]     = bias[n0 + tx * 4 + jj];
        bv[4 + jj] = bias[n0 + 64 + tx * 4 + jj];
    }
#pragma unroll
    for (int i = 0; i < 8; i++) {
        int m = m0 + ty * 4 + (i & 3) + (i >> 2) * 64;
        float* crow = C + (size_t)m * G3 + n0;
        float4 o0, o1;
        o0.x = acc[i][0] + bv[0]; o0.y = acc[i][1] + bv[1];
        o0.z = acc[i][2] + bv[2]; o0.w = acc[i][3] + bv[3];
        o1.x = acc[i][4] + bv[4]; o1.y = acc[i][5] + bv[5];
        o1.z = acc[i][6] + bv[6]; o1.w = acc[i][7] + bv[7];
        *(float4*)(crow + tx * 4)      = o0;
        *(float4*)(crow + 64 + tx * 4) = o1;
    }
}

// ---------------- persistent recurrent scan --------------------------------
// grid 128 = 2 b-tiles x 64 j-blocks (8 j each). 128 threads.
// Thread: 4 b's x 1 j x 3 gates (12 accumulators). One grid barrier per step.
#define SCAN_THREADS 128
#define WS_STRIDE 516
#define SCAN_SMEM ((24 * WS_STRIDE + 512 * 64) * 4)

__global__ __launch_bounds__(SCAN_THREADS, 1)
void k_scan(const float* __restrict__ XP, const float* __restrict__ WuT,
            const float* __restrict__ br, float* __restrict__ seq,
            float* __restrict__ hT0, float* __restrict__ hT1) {
    extern __shared__ float sm[];
    float* Ws = sm;                       // [24][516]
    float* hs = sm + 24 * WS_STRIDE;      // [512][64]  (k-major, b fast)
    const int tid  = threadIdx.x;
    const int bt   = blockIdx.x & 1;      // b-tile (0/1 -> 64 b's)
    const int jblk = blockIdx.x >> 1;     // 0..63
    const int j0   = jblk * 8;
    const int tb   = tid & 15;
    const int tj   = tid >> 4;            // 0..7
    const int bloc = tb * 4;              // local b within 64
    const int b0   = bt * 64 + bloc;
    const int j    = j0 + tj;

    // stage Wu^T rows (z,r,h for this CTA's 8 j's) once for all 256 steps
    for (int r = 0; r < 24; r++) {
        const int g = r >> 3, jj = r & 7;
        const float4* src = (const float4*)(WuT + (size_t)(g * HD + j0 + jj) * HD);
        ((float4*)(Ws + r * WS_STRIDE))[tid] = src[tid];
    }
    __syncthreads();

    const float brz = br[j], brr = br[HD + j], brh = br[2 * HD + j];
    const float* w0 = Ws + (0 * 8 + tj) * WS_STRIDE;
    const float* w1 = Ws + (1 * 8 + tj) * WS_STRIDE;
    const float* w2 = Ws + (2 * 8 + tj) * WS_STRIDE;

    unsigned int bar_target = 0;
    for (int t = 0; t < TD; t++) {
        const float* hcur = (t & 1) ? hT1 : hT0;
        float*       hnxt = (t & 1) ? hT0 : hT1;

        // issue 4 k-chunks of h into smem via cp.async
#pragma unroll
        for (int c = 0; c < 4; c++) {
            const float* src = hcur + (size_t)(c * 128) * BD + bt * 64;
#pragma unroll
            for (int i = 0; i < 16; i++) {
                int idx = tid + i * 128;             // 0..2047 float4s
                int k = idx >> 4, f = idx & 15;
                cp16(hs + (size_t)(c * 128 + k) * 64 + f * 4,
                     src + (size_t)k * BD + f * 4);
            }
            asm volatile("cp.async.commit_group;\n" ::: "memory");
        }

        float acc[4][3];
#pragma unroll
        for (int i = 0; i < 4; i++) { acc[i][0] = 0.f; acc[i][1] = 0.f; acc[i][2] = 0.f; }

#pragma unroll
        for (int c = 0; c < 4; c++) {
            if (c == 0)      asm volatile("cp.async.wait_group 3;\n" ::: "memory");
            else if (c == 1) asm volatile("cp.async.wait_group 2;\n" ::: "memory");
            else if (c == 2) asm volatile("cp.async.wait_group 1;\n" ::: "memory");
            else             asm volatile("cp.async.wait_group 0;\n" ::: "memory");
            __syncthreads();
            const float* hc = hs + (size_t)c * 128 * 64 + bloc;
            const float* wz = w0 + c * 128;
            const float* wr = w1 + c * 128;
            const float* wh = w2 + c * 128;
#pragma unroll 8
            for (int k = 0; k < 128; k++) {
                float4 hv = *(const float4*)(hc + (size_t)k * 64);
                float a = wz[k], b = wr[k], cc = wh[k];
                acc[0][0] += hv.x * a;  acc[1][0] += hv.y * a;
                acc[2][0] += hv.z * a;  acc[3][0] += hv.w * a;
                acc[0][1] += hv.x * b;  acc[1][1] += hv.y * b;
                acc[2][1] += hv.z * b;  acc[3][1] += hv.w * b;
                acc[0][2] += hv.x * cc; acc[1][2] += hv.y * cc;
                acc[2][2] += hv.z * cc; acc[3][2] += hv.w * cc;
            }
        }

        // gate math + state update (h_old comes straight from smem)
#pragma unroll
        for (int i = 0; i < 4; i++) {
            const int b = b0 + i;
            const float* xprow = XP + ((size_t)b * TD + t) * G3;
            float xz = xprow[j], xr = xprow[HD + j], xh = xprow[2 * HD + j];
            float rz = acc[i][0] + brz;
            float rr = acc[i][1] + brr;
            float rh = acc[i][2] + brh;
            float z  = 1.0f / (1.0f + expf(-(xz + rz)));
            float r  = 1.0f / (1.0f + expf(-(xr + rr)));
            float hh = tanhf(xh + r * rh);
            float ho = hs[(size_t)j * 64 + bloc + i];
            float hn = z * ho + (1.0f - z) * hh;
            hnxt[(size_t)j * BD + b] = hn;
            seq[((size_t)b * TD + t) * HD + j] = hn;
        }

        // grid barrier
        bar_target += gridDim.x;
        __syncthreads();
        if (tid == 0) {
            __threadfence();
            atomicAdd(&g_bar, 1u);
            while (atomicAdd(&g_bar, 0u) < bar_target) { }
            __threadfence();
        }
        __syncthreads();
    }
}

// ---------------- launch ---------------------------------------------------
extern "C" void kernel_launch(void* const* d_in, const int* in_sizes, int n_in,
                              void* d_out, int out_size) {
    const float* x      = (const float*)d_in[0];  // [128,256,512]
    const float* kern   = (const float*)d_in[1];  // [3,512,1536]
    const float* rkern  = (const float*)d_in[2];  // [3,512,1536]
    const float* biases = (const float*)d_in[3];  // [3,2,1536]
    float* out = (float*)d_out;

    cudaFuncSetAttribute(k_scan, cudaFuncAttributeMaxDynamicSharedMemorySize, SCAN_SMEM);

    float *XP, *X1, *X2, *WuT, *hT;
    cudaGetSymbolAddress((void**)&XP,  g_XP);
    cudaGetSymbolAddress((void**)&X1,  g_X1);
    cudaGetSymbolAddress((void**)&X2,  g_X2);
    cudaGetSymbolAddress((void**)&WuT, g_WuT);
    cudaGetSymbolAddress((void**)&hT,  g_hT);
    float* hT0 = hT;
    float* hT1 = hT + HD * BD;

    k_trans<<<dim3(G3 / 32, HD / 32, LD), dim3(32, 8)>>>(rkern, WuT);
    k_zero<<<(HD * BD + 255) / 256, 256>>>(hT0, HD * BD);

    const float* cur = x;
    float* outs[3] = {X1, X2, out};
    for (int l = 0; l < LD; l++) {
        const float* Wk = kern + (size_t)l * HD * G3;
        const float* b0 = biases + (size_t)l * 2 * G3;
        k_gemm<<<dim3(G3 / 128, MD / 128), 256>>>(cur, Wk, b0, XP);
        k_rst<<<1, 1>>>();
        k_scan<<<128, SCAN_THREADS, SCAN_SMEM>>>(
            XP, WuT + (size_t)l * G3 * HD, b0 + G3, outs[l], hT0, hT1);
        cur = outs[l];
    }
    k_final<<<(HD * BD + 511) / 512, 512>>>(hT0, out + (size_t)MD * HD);
}